// round 1
// baseline (speedup 1.0000x reference)
#include <cuda_runtime.h>
#include <math_constants.h>

// Tiny transformer, fully fused into ONE kernel / ONE block.
// CONTEXT=5, DIM=32, HEADS=4 (hd=8), NTOK=13, LAYERS=4.
// Thread layout: 160 threads, tid = c*32 + d  (c in [0,5), d in [0,32)).
// All activations live in shared memory; weights are streamed from global
// (L2-resident across graph replays).

#define CTX    5
#define DIM    32
#define NTOK   13
#define HEADS  4
#define HD     8
#define LAYERS 4

__global__ __launch_bounds__(160, 1)
void transformer_fused_kernel(
    const int*   __restrict__ toks,      // [5]
    const float* __restrict__ pos,       // [5,32]
    const float* __restrict__ tokemb,    // [13,32]
    const float* __restrict__ Wq,        // [4,32,32]
    const float* __restrict__ Wk,        // [4,32,32]
    const float* __restrict__ Wv,        // [4,32,32]
    const float* __restrict__ Wp,        // [4,32,32]
    const float* __restrict__ bp,        // [4,32]
    const float* __restrict__ W1,        // [4,32,32]
    const float* __restrict__ b1,        // [4,32]
    const float* __restrict__ W2,        // [4,32,32]
    const float* __restrict__ b2,        // [4,32]
    const float* __restrict__ Wu,        // [32,13]
    const float* __restrict__ bu,        // [13]
    float*       __restrict__ out)       // [5,13]
{
    __shared__ float X [CTX][DIM];
    __shared__ float Q [CTX][DIM];
    __shared__ float K [CTX][DIM];
    __shared__ float V [CTX][DIM];
    __shared__ float S [HEADS][CTX][CTX];
    __shared__ float Yp[CTX][DIM];
    __shared__ float H [CTX][DIM];

    const int tid = threadIdx.x;      // 0..159
    const int c   = tid >> 5;         // 0..4
    const int d   = tid & 31;         // 0..31

    // ---- Embedding: X = tok_embed[toks] + pos_embed ----
    X[c][d] = tokemb[toks[c] * DIM + d] + pos[c * DIM + d];
    __syncthreads();

    #pragma unroll 1
    for (int l = 0; l < LAYERS; ++l) {
        const float* wq = Wq + l * DIM * DIM;
        const float* wk = Wk + l * DIM * DIM;
        const float* wv = Wv + l * DIM * DIM;
        const float* wp = Wp + l * DIM * DIM;
        const float* w1 = W1 + l * DIM * DIM;
        const float* w2 = W2 + l * DIM * DIM;

        // ---- Q, K, V = X @ {Wq,Wk,Wv}  (fused: one pass over X rows) ----
        {
            float q = 0.f, k = 0.f, v = 0.f;
            #pragma unroll
            for (int i = 0; i < DIM; ++i) {
                const float x = X[c][i];
                q = fmaf(x, wq[i * DIM + d], q);
                k = fmaf(x, wk[i * DIM + d], k);
                v = fmaf(x, wv[i * DIM + d], v);
            }
            Q[c][d] = q; K[c][d] = k; V[c][d] = v;
        }
        __syncthreads();

        // ---- Attention scores A[h][q][k] (causal) ----
        if (tid < HEADS * CTX * CTX) {            // 100 threads
            const int h  = tid / (CTX * CTX);
            const int r  = tid % (CTX * CTX);
            const int qq = r / CTX;
            const int kk = r % CTX;
            if (kk <= qq) {
                float a = 0.f;
                #pragma unroll
                for (int i = 0; i < HD; ++i)
                    a = fmaf(Q[qq][h * HD + i], K[kk][h * HD + i], a);
                S[h][qq][kk] = a * 0.17677669529663687f;   // 1/sqrt(32)
            } else {
                S[h][qq][kk] = 0.f;  // masked; softmax below only reads kk<=qq
            }
        }
        __syncthreads();

        // ---- Softmax per (h, q) row over kk in [0, qq] ----
        if (tid < HEADS * CTX) {                  // 20 threads
            const int h  = tid / CTX;
            const int qq = tid % CTX;
            float m = -CUDART_INF_F;
            for (int kk = 0; kk <= qq; ++kk) m = fmaxf(m, S[h][qq][kk]);
            float sum = 0.f;
            for (int kk = 0; kk <= qq; ++kk) {
                const float e = __expf(S[h][qq][kk] - m);
                S[h][qq][kk] = e;
                sum += e;
            }
            const float inv = 1.f / sum;
            for (int kk = 0; kk <= qq; ++kk) S[h][qq][kk] *= inv;
            for (int kk = qq + 1; kk < CTX; ++kk) S[h][qq][kk] = 0.f;
        }
        __syncthreads();

        // ---- Ycat[q][h*8+dh] = sum_k S[h][q][k] * V[k][h*8+dh]  (reuse Q) ----
        {
            const int h = d >> 3;
            float y = 0.f;
            #pragma unroll
            for (int kk = 0; kk < CTX; ++kk)
                y = fmaf(S[h][c][kk], V[kk][d], y);
            Q[c][d] = y;   // Q now holds Ycat
        }
        __syncthreads();

        // ---- Yproj = Ycat @ Wp + bp ----
        {
            float y = bp[l * DIM + d];
            #pragma unroll
            for (int i = 0; i < DIM; ++i)
                y = fmaf(Q[c][i], wp[i * DIM + d], y);
            Yp[c][d] = y;
        }
        __syncthreads();

        // ---- H = relu(Yproj @ W1 + b1) ----
        {
            float y = b1[l * DIM + d];
            #pragma unroll
            for (int i = 0; i < DIM; ++i)
                y = fmaf(Yp[c][i], w1[i * DIM + d], y);
            H[c][d] = fmaxf(y, 0.f);
        }
        __syncthreads();

        // ---- Y = H @ W2 + b2 ;  X = (Y + Yproj) + X ----
        {
            float y = b2[l * DIM + d];
            #pragma unroll
            for (int i = 0; i < DIM; ++i)
                y = fmaf(H[c][i], w2[i * DIM + d], y);
            // thread (c,d) is the only reader AND writer of X[c][d]: no hazard
            X[c][d] = y + Yp[c][d] + X[c][d];
        }
        __syncthreads();
    }

    // ---- Unembed: out[c][t] = X[c] . Wu[:,t] + bu[t] ----
    if (tid < CTX * NTOK) {                       // 65 threads
        const int cc = tid / NTOK;
        const int t  = tid % NTOK;
        float y = bu[t];
        #pragma unroll
        for (int i = 0; i < DIM; ++i)
            y = fmaf(X[cc][i], Wu[i * NTOK + t], y);
        out[tid] = y;
    }
}

extern "C" void kernel_launch(void* const* d_in, const int* in_sizes, int n_in,
                              void* d_out, int out_size) {
    (void)in_sizes; (void)n_in; (void)out_size;
    const int*   toks   = (const int*)  d_in[0];
    const float* pos    = (const float*)d_in[1];
    const float* tokemb = (const float*)d_in[2];
    const float* Wq     = (const float*)d_in[3];
    const float* Wk     = (const float*)d_in[4];
    const float* Wv     = (const float*)d_in[5];
    const float* Wp     = (const float*)d_in[6];
    const float* bp     = (const float*)d_in[7];
    const float* W1     = (const float*)d_in[8];
    const float* b1     = (const float*)d_in[9];
    const float* W2     = (const float*)d_in[10];
    const float* b2     = (const float*)d_in[11];
    const float* Wu     = (const float*)d_in[12];
    const float* bu     = (const float*)d_in[13];
    float* out = (float*)d_out;

    transformer_fused_kernel<<<1, 160>>>(toks, pos, tokemb, Wq, Wk, Wv, Wp, bp,
                                         W1, b1, W2, b2, Wu, bu, out);
}